// round 8
// baseline (speedup 1.0000x reference)
#include <cuda_runtime.h>
#include <cuda_bf16.h>
#include <cstdint>

#define N_NODES 50000
#define HID 128
#define EF 64
#define E_MAX 1600000

// ---------------------------------------------------------------------------
// Scratch (device globals — allocation-free per harness rules)
__device__ float g_P   [(size_t)N_NODES * HID];   // node_feat@W1_top+b1
__device__ float g_P3  [(size_t)N_NODES * HID];   // node_feat@W3_top+b3
__device__ float g_sums[(size_t)N_NODES * HID];   // scatter-add of relu-h
__device__ float g_cnt [N_NODES];                 // float(degree)
__device__ int   g_deg [N_NODES];
__device__ int   g_woff[N_NODES];
__device__ int   g_srow[E_MAX];                   // sorted-by-dest: row
__device__ int   g_scol[E_MAX];                   //   col (source node)
__device__ int   g_seid[E_MAX];                   //   original edge id
__device__ float g_W23 [128 * 128];               // W2 @ W3_bot (fp32)
__device__ float g_b23 [128];                     // b2 @ W3_bot
// bf16 hi/lo weight images, [N][K] K-major 128B rows, SW128-swizzled.
// [0,16K) B1hi | [16K,32K) B1lo | then 4 node weights x 64KB each.
// widx: 0=W1_top 1=W3_top 2=W23 3=W4
__device__ __align__(16) unsigned char g_WB[32768 + 4 * 65536];

__device__ __forceinline__ uint32_t smem_u32(const void* p) {
    uint32_t a;
    asm("{ .reg .u64 t; cvta.to.shared.u64 t, %1; cvt.u32.u64 %0, t; }"
        : "=r"(a) : "l"(p));
    return a;
}
__device__ __forceinline__ uint32_t swz(uint32_t b) { return b ^ ((b >> 3) & 0x70); }

__device__ __forceinline__ void ldsm_x4(uint32_t* r, uint32_t addr) {
    asm volatile("ldmatrix.sync.aligned.m8n8.x4.shared.b16 {%0,%1,%2,%3}, [%4];"
                 : "=r"(r[0]), "=r"(r[1]), "=r"(r[2]), "=r"(r[3]) : "r"(addr));
}
__device__ __forceinline__ void mma_bf16(float* d, const uint32_t* a, const uint32_t* b) {
    asm volatile("mma.sync.aligned.m16n8k16.row.col.f32.bf16.bf16.f32 "
                 "{%0,%1,%2,%3}, {%4,%5,%6,%7}, {%8,%9}, {%0,%1,%2,%3};"
                 : "+f"(d[0]), "+f"(d[1]), "+f"(d[2]), "+f"(d[3])
                 : "r"(a[0]), "r"(a[1]), "r"(a[2]), "r"(a[3]), "r"(b[0]), "r"(b[1]));
}
__device__ __forceinline__ uint32_t pack_bf16x2(float x, float y) {
    __nv_bfloat162 p = {__float2bfloat16(x), __float2bfloat16(y)};
    return *(uint32_t*)&p;
}
__device__ __forceinline__ void split2(float x, float y, uint32_t& hi, uint32_t& lo) {
    __nv_bfloat16 hx = __float2bfloat16(x), hy = __float2bfloat16(y);
    __nv_bfloat162 ph = {hx, hy};
    hi = *(uint32_t*)&ph;
    lo = pack_bf16x2(x - __bfloat162float(hx), y - __bfloat162float(hy));
}
__device__ __forceinline__ void split8(float4 v0, float4 v1, uint4& hi, uint4& lo) {
    split2(v0.x, v0.y, hi.x, lo.x);
    split2(v0.z, v0.w, hi.y, lo.y);
    split2(v1.x, v1.y, hi.z, lo.z);
    split2(v1.z, v1.w, hi.w, lo.w);
}

// Shared K=128 bf16x3 GEMM core with x4 B-operand ldmatrix.
__device__ __forceinline__ void gemm128_core(
    uint32_t smb, uint32_t aoff, uint32_t woff, int lid,
    int arow, int akof, float acc[16][4]) {
    const int ntoff = lid >> 4;
    const int brow = lid & 7;
    const int bkof = ((lid >> 3) & 1) << 4;
    #pragma unroll
    for (int kt = 0; kt < 8; kt++) {
        const int chunk = (kt >> 2) * 16384;
        const int kb = (kt & 3) * 32;
        uint32_t ahi[4], alo[4];
        ldsm_x4(ahi, smb + aoff + chunk + swz(arow * 128 + kb + akof));
        ldsm_x4(alo, smb + aoff + 32768 + chunk + swz(arow * 128 + kb + akof));
        #pragma unroll
        for (int nt = 0; nt < 16; nt += 2) {
            uint32_t bo = swz(((nt + ntoff) * 8 + brow) * 128 + kb + bkof);
            uint32_t bh[4], bl[4];
            ldsm_x4(bh, smb + woff + chunk + bo);
            ldsm_x4(bl, smb + woff + 32768 + chunk + bo);
            mma_bf16(acc[nt],     ahi, bh);
            mma_bf16(acc[nt],     ahi, bl);
            mma_bf16(acc[nt],     alo, bh);
            mma_bf16(acc[nt + 1], ahi, bh + 2);
            mma_bf16(acc[nt + 1], ahi, bl + 2);
            mma_bf16(acc[nt + 1], alo, bh + 2);
        }
    }
}

// ---------------------------------------------------------------------------
__global__ void zero_kernel() {
    const size_t total4 = (size_t)N_NODES * HID / 4;
    float4* s = (float4*)g_sums;
    const float4 z = make_float4(0.f, 0.f, 0.f, 0.f);
    for (size_t i = (size_t)blockIdx.x * blockDim.x + threadIdx.x; i < total4;
         i += (size_t)gridDim.x * blockDim.x)
        s[i] = z;
    for (int i = blockIdx.x * blockDim.x + threadIdx.x; i < N_NODES;
         i += gridDim.x * blockDim.x)
        g_deg[i] = 0;
}

// ---------------------------------------------------------------------------
__global__ void count_kernel(const int* __restrict__ eidx, int E) {
    for (int e = blockIdx.x * blockDim.x + threadIdx.x; e < E;
         e += gridDim.x * blockDim.x)
        atomicAdd(&g_deg[eidx[e]], 1);
}

// Single-block exclusive scan of degrees -> g_woff; also g_cnt = float(deg).
__global__ __launch_bounds__(1024, 1)
void scan_kernel() {
    __shared__ int partials[1024];
    const int tid = threadIdx.x;
    const int CH = (N_NODES + 1023) / 1024;   // 49
    const int base = tid * CH;
    int sum = 0;
    for (int i = 0; i < CH; i++) {
        int idx = base + i;
        if (idx < N_NODES) sum += g_deg[idx];
    }
    partials[tid] = sum;
    __syncthreads();
    for (int s = 1; s < 1024; s <<= 1) {
        int t = (tid >= s) ? partials[tid - s] : 0;
        __syncthreads();
        if (tid >= s) partials[tid] += t;
        __syncthreads();
    }
    int run = partials[tid] - sum;   // exclusive prefix of this chunk
    for (int i = 0; i < CH; i++) {
        int idx = base + i;
        if (idx < N_NODES) {
            g_woff[idx] = run;
            int d = g_deg[idx];
            g_cnt[idx] = (float)d;
            run += d;
        }
    }
}

__global__ void permute_kernel(const int* __restrict__ eidx, int E) {
    for (int e = blockIdx.x * blockDim.x + threadIdx.x; e < E;
         e += gridDim.x * blockDim.x) {
        int r = eidx[e];
        int pos = atomicAdd(&g_woff[r], 1);
        g_srow[pos] = r;
        g_scol[pos] = eidx[(size_t)E + e];
        g_seid[pos] = e;
    }
}

// ---------------------------------------------------------------------------
// W23 = W2 @ W3[128:256], b23 = b2 @ W3[128:256]
__global__ void prep1_kernel(const float* __restrict__ W2,
                             const float* __restrict__ W3,
                             const float* __restrict__ b2) {
    __shared__ float srow[128];
    const int r = blockIdx.x;
    const int c = threadIdx.x;
    srow[c] = (r < 128) ? W2[r * 128 + c] : b2[c];
    __syncthreads();
    float acc = 0.f;
    #pragma unroll 4
    for (int k = 0; k < 128; k++)
        acc += srow[k] * W3[(128 + k) * 128 + c];
    if (r < 128) g_W23[r * 128 + c] = acc;
    else         g_b23[c] = acc;
}

// ---------------------------------------------------------------------------
__global__ void prep2_kernel(const float* __restrict__ W1,
                             const float* __restrict__ W3,
                             const float* __restrict__ W4) {
    const int tid = blockIdx.x * blockDim.x + threadIdx.x;
    const int nth = gridDim.x * blockDim.x;
    for (int i = tid; i < 128 * 64; i += nth) {       // edge B1 = W1 rows 128..191
        int n = i >> 6, k = i & 63;
        float v = W1[(128 + k) * 128 + n];
        __nv_bfloat16 h = __float2bfloat16(v);
        __nv_bfloat16 l = __float2bfloat16(v - __bfloat162float(h));
        uint32_t off = swz(n * 128 + k * 2);
        *(__nv_bfloat16*)(g_WB + off)         = h;
        *(__nv_bfloat16*)(g_WB + 16384 + off) = l;
    }
    for (int i = tid; i < 4 * 128 * 128; i += nth) {  // node weights
        int widx = i >> 14, j = i & 16383;
        int n = j >> 7, k = j & 127;
        float v;
        if      (widx == 0) v = W1[k * 128 + n];
        else if (widx == 1) v = W3[k * 128 + n];
        else if (widx == 2) v = g_W23[k * 128 + n];
        else                v = W4[k * 128 + n];
        __nv_bfloat16 h = __float2bfloat16(v);
        __nv_bfloat16 l = __float2bfloat16(v - __bfloat162float(h));
        int c = k >> 6, kk = k & 63;
        uint32_t off = swz(n * 128 + kk * 2);
        unsigned char* base = g_WB + 32768 + widx * 65536;
        *(__nv_bfloat16*)(base + c * 16384 + off)         = h;
        *(__nv_bfloat16*)(base + 32768 + c * 16384 + off) = l;
    }
}

// ---------------------------------------------------------------------------
// pre_both: stage node_feat once; P = nf@W1t + b1; P3 = nf@W3t + b3.
#define PB_W 0
#define PB_A 65536
#define PB_BIAS 131072
#define PB_SMEM (131072 + 1024)

__global__ __launch_bounds__(256, 1)
void pre_both_kernel(const float* __restrict__ A, const float* __restrict__ b1,
                     const float* __restrict__ b3) {
    extern __shared__ char smc[];
    const uint32_t smb = smem_u32(smc);
    const int tid = threadIdx.x;
    const int wid = tid >> 5;
    const int lid = tid & 31;
    float* s_b1 = (float*)(smc + PB_BIAS);
    float* s_b3 = s_b1 + 128;

    {
        const float4* src = (const float4*)(g_WB + 32768);
        float4* dst = (float4*)smc;
        #pragma unroll
        for (int i = 0; i < 16; i++) dst[tid + 256 * i] = src[tid + 256 * i];
    }
    if (tid < 128) { s_b1[tid] = b1[tid]; s_b3[tid] = b3[tid]; }

    const int m0 = blockIdx.x * 128;
    {
        const int r = tid >> 1;
        const int chunk = tid & 1;
        const int gr = m0 + r;
        const bool valid = gr < N_NODES;
        const float* src = A + (size_t)gr * 128 + chunk * 64;
        #pragma unroll
        for (int j = 0; j < 8; j++) {
            float4 v0 = valid ? *(const float4*)(src + j * 8)
                              : make_float4(0.f, 0.f, 0.f, 0.f);
            float4 v1 = valid ? *(const float4*)(src + j * 8 + 4)
                              : make_float4(0.f, 0.f, 0.f, 0.f);
            uint4 hi, lo;
            split8(v0, v1, hi, lo);
            uint32_t off = swz(r * 128 + j * 16);
            *(uint4*)(smc + PB_A + chunk * 16384 + off) = hi;
            *(uint4*)(smc + PB_A + 32768 + chunk * 16384 + off) = lo;
        }
    }
    __syncthreads();

    const int wr0 = wid * 16;
    const int qr = lid >> 2, qc = (lid & 3) * 2;
    const int r0 = wr0 + qr, r1 = r0 + 8;
    const int am = lid >> 3;
    const int arow = wr0 + ((am & 1) << 3) + (lid & 7);
    const int akof = (am >> 1) << 4;
    const int gr0 = m0 + r0, gr1 = m0 + r1;

    float acc[16][4];
    #pragma unroll
    for (int nt = 0; nt < 16; nt++)
        #pragma unroll
        for (int v = 0; v < 4; v++) acc[nt][v] = 0.f;
    gemm128_core(smb, PB_A, PB_W, lid, arow, akof, acc);
    #pragma unroll
    for (int nt = 0; nt < 16; nt++) {
        const int c = nt * 8 + qc;
        if (gr0 < N_NODES)
            *(float2*)(g_P + (size_t)gr0 * 128 + c) = make_float2(
                acc[nt][0] + s_b1[c], acc[nt][1] + s_b1[c + 1]);
        if (gr1 < N_NODES)
            *(float2*)(g_P + (size_t)gr1 * 128 + c) = make_float2(
                acc[nt][2] + s_b1[c], acc[nt][3] + s_b1[c + 1]);
    }
    __syncthreads();
    {
        const float4* src = (const float4*)(g_WB + 32768 + 65536);
        float4* dst = (float4*)smc;
        #pragma unroll
        for (int i = 0; i < 16; i++) dst[tid + 256 * i] = src[tid + 256 * i];
    }
    __syncthreads();
    #pragma unroll
    for (int nt = 0; nt < 16; nt++)
        #pragma unroll
        for (int v = 0; v < 4; v++) acc[nt][v] = 0.f;
    gemm128_core(smb, PB_A, PB_W, lid, arow, akof, acc);
    #pragma unroll
    for (int nt = 0; nt < 16; nt++) {
        const int c = nt * 8 + qc;
        if (gr0 < N_NODES)
            *(float2*)(g_P3 + (size_t)gr0 * 128 + c) = make_float2(
                acc[nt][0] + s_b3[c], acc[nt][1] + s_b3[c + 1]);
        if (gr1 < N_NODES)
            *(float2*)(g_P3 + (size_t)gr1 * 128 + c) = make_float2(
                acc[nt][2] + s_b3[c], acc[nt][3] + s_b3[c + 1]);
    }
}

// ---------------------------------------------------------------------------
// node_fused: mean = sums/max(cnt,1); T = relu(P3 + mean@W23 + flag*b23);
// out = T@W4 + b4.
__global__ __launch_bounds__(256, 1)
void node_fused_kernel(const float* __restrict__ b4, float* __restrict__ out) {
    extern __shared__ char smc[];
    const uint32_t smb = smem_u32(smc);
    const int tid = threadIdx.x;
    const int wid = tid >> 5;
    const int lid = tid & 31;
    float* s_b23 = (float*)(smc + PB_BIAS);
    float* s_b4  = s_b23 + 128;

    {
        const float4* src = (const float4*)(g_WB + 32768 + 2 * 65536);
        float4* dst = (float4*)smc;
        #pragma unroll
        for (int i = 0; i < 16; i++) dst[tid + 256 * i] = src[tid + 256 * i];
    }
    if (tid < 128) { s_b23[tid] = g_b23[tid]; s_b4[tid] = b4[tid]; }

    const int m0 = blockIdx.x * 128;
    {
        const int r = tid >> 1;
        const int chunk = tid & 1;
        const int gr = m0 + r;
        const bool valid = gr < N_NODES;
        float s = valid ? 1.f / fmaxf(g_cnt[gr], 1.f) : 0.f;
        const float* src = g_sums + (size_t)gr * 128 + chunk * 64;
        #pragma unroll
        for (int j = 0; j < 8; j++) {
            float4 v0 = valid ? *(const float4*)(src + j * 8)
                              : make_float4(0.f, 0.f, 0.f, 0.f);
            float4 v1 = valid ? *(const float4*)(src + j * 8 + 4)
                              : make_float4(0.f, 0.f, 0.f, 0.f);
            v0.x *= s; v0.y *= s; v0.z *= s; v0.w *= s;
            v1.x *= s; v1.y *= s; v1.z *= s; v1.w *= s;
            uint4 hi, lo;
            split8(v0, v1, hi, lo);
            uint32_t off = swz(r * 128 + j * 16);
            *(uint4*)(smc + PB_A + chunk * 16384 + off) = hi;
            *(uint4*)(smc + PB_A + 32768 + chunk * 16384 + off) = lo;
        }
    }
    __syncthreads();

    const int wr0 = wid * 16;
    const int qr = lid >> 2, qc = (lid & 3) * 2;
    const int r0 = wr0 + qr, r1 = r0 + 8;
    const int am = lid >> 3;
    const int arow = wr0 + ((am & 1) << 3) + (lid & 7);
    const int akof = (am >> 1) << 4;
    const int gr0 = m0 + r0, gr1 = m0 + r1;

    float acc[16][4];
    #pragma unroll
    for (int nt = 0; nt < 16; nt++)
        #pragma unroll
        for (int v = 0; v < 4; v++) acc[nt][v] = 0.f;
    gemm128_core(smb, PB_A, PB_W, lid, arow, akof, acc);

    {
        const float f0 = (gr0 < N_NODES && g_cnt[gr0] > 0.f) ? 1.f : 0.f;
        const float f1 = (gr1 < N_NODES && g_cnt[gr1] > 0.f) ? 1.f : 0.f;
        #pragma unroll
        for (int nt = 0; nt < 16; nt++) {
            const int c = nt * 8 + qc;
            float t00 = 0.f, t01 = 0.f, t10 = 0.f, t11 = 0.f;
            if (gr0 < N_NODES) {
                float2 p = *(const float2*)(g_P3 + (size_t)gr0 * 128 + c);
                t00 = fmaxf(p.x + acc[nt][0] + f0 * s_b23[c], 0.f);
                t01 = fmaxf(p.y + acc[nt][1] + f0 * s_b23[c + 1], 0.f);
            }
            if (gr1 < N_NODES) {
                float2 p = *(const float2*)(g_P3 + (size_t)gr1 * 128 + c);
                t10 = fmaxf(p.x + acc[nt][2] + f1 * s_b23[c], 0.f);
                t11 = fmaxf(p.y + acc[nt][3] + f1 * s_b23[c + 1], 0.f);
            }
            uint32_t hi0, lo0, hi1, lo1;
            split2(t00, t01, hi0, lo0);
            split2(t10, t11, hi1, lo1);
            const int chunk = (c >> 6) * 16384;
            const int kk2 = (c & 63) * 2;
            *(uint32_t*)(smc + PB_A + chunk + swz(r0 * 128 + kk2)) = hi0;
            *(uint32_t*)(smc + PB_A + chunk + swz(r1 * 128 + kk2)) = hi1;
            *(uint32_t*)(smc + PB_A + 32768 + chunk + swz(r0 * 128 + kk2)) = lo0;
            *(uint32_t*)(smc + PB_A + 32768 + chunk + swz(r1 * 128 + kk2)) = lo1;
        }
    }
    __syncthreads();
    {
        const float4* src = (const float4*)(g_WB + 32768 + 3 * 65536);
        float4* dst = (float4*)smc;
        #pragma unroll
        for (int i = 0; i < 16; i++) dst[tid + 256 * i] = src[tid + 256 * i];
    }
    __syncthreads();
    #pragma unroll
    for (int nt = 0; nt < 16; nt++)
        #pragma unroll
        for (int v = 0; v < 4; v++) acc[nt][v] = 0.f;
    gemm128_core(smb, PB_A, PB_W, lid, arow, akof, acc);
    #pragma unroll
    for (int nt = 0; nt < 16; nt++) {
        const int c = nt * 8 + qc;
        if (gr0 < N_NODES)
            *(float2*)(out + (size_t)gr0 * 128 + c) = make_float2(
                acc[nt][0] + s_b4[c], acc[nt][1] + s_b4[c + 1]);
        if (gr1 < N_NODES)
            *(float2*)(out + (size_t)gr1 * 128 + c) = make_float2(
                acc[nt][2] + s_b4[c], acc[nt][3] + s_b4[c + 1]);
    }
}

// ---------------------------------------------------------------------------
// Edge kernel over DEST-SORTED edges.
// D1 = ea[eid]@W1_bot (bf16x3, K=64); h = relu(D1 + P[col]); rows sharing a
// destination are run-length reduced in SMEM before ONE RED per segment.
// SMEM: [0,16K) B1hi | 16K B1lo | 32K Ahi | 48K Alo | 64K msg(32K) | 96K idx
#define SM_B1HI 0
#define SM_B1LO 16384
#define SM_A    32768
#define SM_MSG  65536
#define SM_IDX  98304
#define EDGE_SMEM_BYTES (98304 + 1024)

__global__ __launch_bounds__(256, 2)
void edge_kernel_mma(const float* __restrict__ ea, int E, int ntiles) {
    extern __shared__ char smc[];
    const uint32_t smb = smem_u32(smc);
    const int tid = threadIdx.x;
    const int wid = tid >> 5;
    const int lid = tid & 31;

    int* s_row = (int*)(smc + SM_IDX);
    int* s_col = s_row + 128;
    float* msgf = (float*)(smc + SM_MSG);

    {   // weights once (32 KB)
        const float4* src = (const float4*)g_WB;
        float4* dst = (float4*)smc;
        for (int i = tid; i < 2048; i += 256) dst[i] = src[i];
    }

    // staging lane geometry (2 threads/row)
    const int st_r = tid >> 1;
    const int st_half = tid & 1;

    // MMA lane geometry
    const int wr0 = wid * 16;
    const int qr = lid >> 2;
    const int r0 = wr0 + qr, r1 = r0 + 8;
    const int am = lid >> 3;
    const int arow = wr0 + ((am & 1) << 3) + (lid & 7);
    const int akof = (am >> 1) << 4;
    const int ntoff = lid >> 4;
    const int brow = lid & 7;
    const int bkof = ((lid >> 3) & 1) << 4;
    // epilogue shuffle geometry
    const int cboff = (lid & 2) ? 4 : 0;
    const bool evenlane = ((lid & 1) == 0);
    const int myrow = evenlane ? r0 : r1;
    const int mrot = (myrow & 15) * 4;
    // reduce geometry: quad q (4 cols within 64-col half), 8-row chunk
    const int rq = tid & 15;
    const int rbase = (tid >> 4) * 8;

    for (int tile = blockIdx.x; tile < ntiles; tile += gridDim.x) {
        const int e0 = tile * 128;

        // ---- stage indices + edge_attr (gathered by sorted eid) ----
        if (tid < 128) {
            int p = e0 + tid;
            s_row[tid] = (p < E) ? g_srow[p] : 0;
        } else {
            int t = tid - 128, p = e0 + t;
            s_col[t] = (p < E) ? g_scol[p] : 0;
        }
        {
            const int p = e0 + st_r;
            const bool valid = p < E;
            const int eid = valid ? g_seid[p] : 0;
            const float* src = ea + (size_t)eid * EF + st_half * 32;
            #pragma unroll
            for (int j = 0; j < 4; j++) {
                float4 v0 = valid ? *(const float4*)(src + j * 8)
                                  : make_float4(0.f, 0.f, 0.f, 0.f);
                float4 v1 = valid ? *(const float4*)(src + j * 8 + 4)
                                  : make_float4(0.f, 0.f, 0.f, 0.f);
                uint4 hi, lo;
                split8(v0, v1, hi, lo);
                uint32_t off = swz(st_r * 128 + st_half * 64 + j * 16);
                *(uint4*)(smc + SM_A + off) = hi;
                *(uint4*)(smc + SM_A + 16384 + off) = lo;
            }
        }
        __syncthreads();

        // ---- GEMM1 ----
        float acc[16][4];
        #pragma unroll
        for (int nt = 0; nt < 16; nt++)
            #pragma unroll
            for (int v = 0; v < 4; v++) acc[nt][v] = 0.f;
        #pragma unroll
        for (int kt = 0; kt < 4; kt++) {
            const int kb = kt * 32;
            uint32_t ahi[4], alo[4];
            ldsm_x4(ahi, smb + SM_A + swz(arow * 128 + kb + akof));
            ldsm_x4(alo, smb + SM_A + 16384 + swz(arow * 128 + kb + akof));
            #pragma unroll
            for (int nt = 0; nt < 16; nt += 2) {
                uint32_t bo = swz(((nt + ntoff) * 8 + brow) * 128 + kb + bkof);
                uint32_t bh[4], bl[4];
                ldsm_x4(bh, smb + SM_B1HI + bo);
                ldsm_x4(bl, smb + SM_B1LO + bo);
                mma_bf16(acc[nt],     ahi, bh);
                mma_bf16(acc[nt],     ahi, bl);
                mma_bf16(acc[nt],     alo, bh);
                mma_bf16(acc[nt + 1], ahi, bh + 2);
                mma_bf16(acc[nt + 1], ahi, bl + 2);
                mma_bf16(acc[nt + 1], alo, bh + 2);
            }
        }

        // ---- epilogue in two 64-column halves ----
        const bool vrow = (e0 + myrow < E);
        const float* Pmy = g_P + (size_t)s_col[myrow] * 128 + cboff;
        #pragma unroll
        for (int h = 0; h < 2; h++) {
            // write relu(D1 + P) into msg (rotated rows)
            #pragma unroll
            for (int ntl = 0; ntl < 8; ntl++) {
                const int nt = h * 8 + ntl;
                float sA = evenlane ? acc[nt][2] : acc[nt][0];
                float sB = evenlane ? acc[nt][3] : acc[nt][1];
                float rA = __shfl_xor_sync(0xFFFFFFFFu, sA, 1);
                float rB = __shfl_xor_sync(0xFFFFFFFFu, sB, 1);
                float4 v = evenlane
                    ? make_float4(acc[nt][0], acc[nt][1], rA, rB)
                    : make_float4(rA, rB, acc[nt][2], acc[nt][3]);
                if (vrow) {
                    float4 pv = *(const float4*)(Pmy + h * 64 + ntl * 8);
                    v.x = fmaxf(v.x + pv.x, 0.f);
                    v.y = fmaxf(v.y + pv.y, 0.f);
                    v.z = fmaxf(v.z + pv.z, 0.f);
                    v.w = fmaxf(v.w + pv.w, 0.f);
                } else {
                    v = make_float4(0.f, 0.f, 0.f, 0.f);
                }
                const int cw = ntl * 8 + cboff;
                *(float4*)(msgf + myrow * 64 + ((cw + mrot) & 63)) = v;
            }
            __syncthreads();
            // run-length segmented reduce over 8 sorted rows, RED per segment
            {
                int r = rbase;
                int cur = s_row[r];
                float4 a = *(const float4*)(msgf + r * 64 + ((rq * 4 + (r & 15) * 4) & 63));
                #pragma unroll
                for (int i = 1; i < 8; i++) {
                    r = rbase + i;
                    int d = s_row[r];
                    float4 v = *(const float4*)(msgf + r * 64 + ((rq * 4 + (r & 15) * 4) & 63));
                    if (d == cur) {
                        a.x += v.x; a.y += v.y; a.z += v.z; a.w += v.w;
                    } else {
                        atomicAdd((float4*)(g_sums + (size_t)cur * 128 + h * 64 + rq * 4), a);
                        cur = d; a = v;
                    }
                }
                atomicAdd((float4*)(g_sums + (size_t)cur * 128 + h * 64 + rq * 4), a);
            }
            __syncthreads();   // msg free for next half / next tile's A restage
        }
    }
}

// ---------------------------------------------------------------------------
extern "C" void kernel_launch(void* const* d_in, const int* in_sizes, int n_in,
                              void* d_out, int out_size) {
    const float* node_feat = (const float*)d_in[0];
    const int*   eidx      = (const int*)d_in[1];   // int32 (JAX x64 disabled)
    const float* ea        = (const float*)d_in[2];
    const float* W1 = (const float*)d_in[3];
    const float* b1 = (const float*)d_in[4];
    const float* W2 = (const float*)d_in[5];
    const float* b2 = (const float*)d_in[6];
    const float* W3 = (const float*)d_in[7];
    const float* b3 = (const float*)d_in[8];
    const float* W4 = (const float*)d_in[9];
    const float* b4 = (const float*)d_in[10];
    float* out = (float*)d_out;

    const int E = in_sizes[1] / 2;
    const int NBN = (N_NODES + 127) / 128;   // 391
    const int NBE = (E + 127) / 128;         // 12500

    cudaFuncSetAttribute(pre_both_kernel,
                         cudaFuncAttributeMaxDynamicSharedMemorySize, PB_SMEM);
    cudaFuncSetAttribute(node_fused_kernel,
                         cudaFuncAttributeMaxDynamicSharedMemorySize, PB_SMEM);
    cudaFuncSetAttribute(edge_kernel_mma,
                         cudaFuncAttributeMaxDynamicSharedMemorySize, EDGE_SMEM_BYTES);

    zero_kernel<<<1024, 256>>>();
    count_kernel<<<592, 256>>>(eidx, E);
    prep1_kernel<<<129, 128>>>(W2, W3, b2);
    prep2_kernel<<<64, 256>>>(W1, W3, W4);
    scan_kernel<<<1, 1024>>>();
    permute_kernel<<<592, 256>>>(eidx, E);
    pre_both_kernel<<<NBN, 256, PB_SMEM>>>(node_feat, b1, b3);
    edge_kernel_mma<<<296, 256, EDGE_SMEM_BYTES>>>(ea, E, NBE);
    node_fused_kernel<<<NBN, 256, PB_SMEM>>>(b4, out);
}

// round 9
// speedup vs baseline: 1.1499x; 1.1499x over previous
#include <cuda_runtime.h>
#include <cuda_bf16.h>
#include <cstdint>

#define N_NODES 50000
#define HID 128
#define EF 64

// ---------------------------------------------------------------------------
// Scratch (device globals — allocation-free per harness rules)
__device__ float g_P   [(size_t)N_NODES * HID];   // node_feat@W1_top+b1
__device__ float g_P3  [(size_t)N_NODES * HID];   // node_feat@W3_top+b3
__device__ float g_sums[(size_t)N_NODES * HID];   // scatter-add of relu-h
__device__ float g_cnt [N_NODES];
__device__ float g_W23 [128 * 128];               // W2 @ W3_bot (fp32)
__device__ float g_b23 [128];                     // b2 @ W3_bot
// bf16 hi/lo weight images, [N][K] K-major 128B rows, SW128-swizzled.
// [0,16K) B1hi | [16K,32K) B1lo | then 4 node weights x 64KB each.
// widx: 0=W1_top 1=W3_top 2=W23 3=W4
__device__ __align__(16) unsigned char g_WB[32768 + 4 * 65536];

__device__ __forceinline__ uint32_t smem_u32(const void* p) {
    uint32_t a;
    asm("{ .reg .u64 t; cvta.to.shared.u64 t, %1; cvt.u32.u64 %0, t; }"
        : "=r"(a) : "l"(p));
    return a;
}
__device__ __forceinline__ uint32_t swz(uint32_t b) { return b ^ ((b >> 3) & 0x70); }

__device__ __forceinline__ void ldsm_x4(uint32_t* r, uint32_t addr) {
    asm volatile("ldmatrix.sync.aligned.m8n8.x4.shared.b16 {%0,%1,%2,%3}, [%4];"
                 : "=r"(r[0]), "=r"(r[1]), "=r"(r[2]), "=r"(r[3]) : "r"(addr));
}
__device__ __forceinline__ void mma_bf16(float* d, const uint32_t* a, const uint32_t* b) {
    asm volatile("mma.sync.aligned.m16n8k16.row.col.f32.bf16.bf16.f32 "
                 "{%0,%1,%2,%3}, {%4,%5,%6,%7}, {%8,%9}, {%0,%1,%2,%3};"
                 : "+f"(d[0]), "+f"(d[1]), "+f"(d[2]), "+f"(d[3])
                 : "r"(a[0]), "r"(a[1]), "r"(a[2]), "r"(a[3]), "r"(b[0]), "r"(b[1]));
}
__device__ __forceinline__ uint32_t pack_bf16x2(float x, float y) {
    __nv_bfloat162 p = {__float2bfloat16(x), __float2bfloat16(y)};
    return *(uint32_t*)&p;
}
__device__ __forceinline__ void split2(float x, float y, uint32_t& hi, uint32_t& lo) {
    __nv_bfloat16 hx = __float2bfloat16(x), hy = __float2bfloat16(y);
    __nv_bfloat162 ph = {hx, hy};
    hi = *(uint32_t*)&ph;
    lo = pack_bf16x2(x - __bfloat162float(hx), y - __bfloat162float(hy));
}
__device__ __forceinline__ void split8(float4 v0, float4 v1, uint4& hi, uint4& lo) {
    split2(v0.x, v0.y, hi.x, lo.x);
    split2(v0.z, v0.w, hi.y, lo.y);
    split2(v1.x, v1.y, hi.z, lo.z);
    split2(v1.z, v1.w, hi.w, lo.w);
}

// Shared K=128 bf16x3 GEMM core with x4 B-operand ldmatrix (256-thr kernels).
__device__ __forceinline__ void gemm128_core(
    uint32_t smb, uint32_t aoff, uint32_t woff, int lid,
    int arow, int akof, float acc[16][4]) {
    const int ntoff = lid >> 4;
    const int brow = lid & 7;
    const int bkof = ((lid >> 3) & 1) << 4;
    #pragma unroll
    for (int kt = 0; kt < 8; kt++) {
        const int chunk = (kt >> 2) * 16384;
        const int kb = (kt & 3) * 32;
        uint32_t ahi[4], alo[4];
        ldsm_x4(ahi, smb + aoff + chunk + swz(arow * 128 + kb + akof));
        ldsm_x4(alo, smb + aoff + 32768 + chunk + swz(arow * 128 + kb + akof));
        #pragma unroll
        for (int nt = 0; nt < 16; nt += 2) {
            uint32_t bo = swz(((nt + ntoff) * 8 + brow) * 128 + kb + bkof);
            uint32_t bh[4], bl[4];
            ldsm_x4(bh, smb + woff + chunk + bo);
            ldsm_x4(bl, smb + woff + 32768 + chunk + bo);
            mma_bf16(acc[nt],     ahi, bh);
            mma_bf16(acc[nt],     ahi, bl);
            mma_bf16(acc[nt],     alo, bh);
            mma_bf16(acc[nt + 1], ahi, bh + 2);
            mma_bf16(acc[nt + 1], ahi, bl + 2);
            mma_bf16(acc[nt + 1], alo, bh + 2);
        }
    }
}

// ---------------------------------------------------------------------------
__global__ void zero_kernel() {
    const size_t total4 = (size_t)N_NODES * HID / 4;
    float4* s = (float4*)g_sums;
    const float4 z = make_float4(0.f, 0.f, 0.f, 0.f);
    for (size_t i = (size_t)blockIdx.x * blockDim.x + threadIdx.x; i < total4;
         i += (size_t)gridDim.x * blockDim.x)
        s[i] = z;
    for (int i = blockIdx.x * blockDim.x + threadIdx.x; i < N_NODES;
         i += gridDim.x * blockDim.x)
        g_cnt[i] = 0.f;
}

// ---------------------------------------------------------------------------
// W23 = W2 @ W3[128:256], b23 = b2 @ W3[128:256]
__global__ void prep1_kernel(const float* __restrict__ W2,
                             const float* __restrict__ W3,
                             const float* __restrict__ b2) {
    __shared__ float srow[128];
    const int r = blockIdx.x;
    const int c = threadIdx.x;
    srow[c] = (r < 128) ? W2[r * 128 + c] : b2[c];
    __syncthreads();
    float acc = 0.f;
    #pragma unroll 4
    for (int k = 0; k < 128; k++)
        acc += srow[k] * W3[(128 + k) * 128 + c];
    if (r < 128) g_W23[r * 128 + c] = acc;
    else         g_b23[c] = acc;
}

// ---------------------------------------------------------------------------
__global__ void prep2_kernel(const float* __restrict__ W1,
                             const float* __restrict__ W3,
                             const float* __restrict__ W4) {
    const int tid = blockIdx.x * blockDim.x + threadIdx.x;
    const int nth = gridDim.x * blockDim.x;
    for (int i = tid; i < 128 * 64; i += nth) {       // edge B1 = W1 rows 128..191
        int n = i >> 6, k = i & 63;
        float v = W1[(128 + k) * 128 + n];
        __nv_bfloat16 h = __float2bfloat16(v);
        __nv_bfloat16 l = __float2bfloat16(v - __bfloat162float(h));
        uint32_t off = swz(n * 128 + k * 2);
        *(__nv_bfloat16*)(g_WB + off)         = h;
        *(__nv_bfloat16*)(g_WB + 16384 + off) = l;
    }
    for (int i = tid; i < 4 * 128 * 128; i += nth) {  // node weights
        int widx = i >> 14, j = i & 16383;
        int n = j >> 7, k = j & 127;
        float v;
        if      (widx == 0) v = W1[k * 128 + n];
        else if (widx == 1) v = W3[k * 128 + n];
        else if (widx == 2) v = g_W23[k * 128 + n];
        else                v = W4[k * 128 + n];
        __nv_bfloat16 h = __float2bfloat16(v);
        __nv_bfloat16 l = __float2bfloat16(v - __bfloat162float(h));
        int c = k >> 6, kk = k & 63;
        uint32_t off = swz(n * 128 + kk * 2);
        unsigned char* base = g_WB + 32768 + widx * 65536;
        *(__nv_bfloat16*)(base + c * 16384 + off)         = h;
        *(__nv_bfloat16*)(base + 32768 + c * 16384 + off) = l;
    }
}

// ---------------------------------------------------------------------------
// pre_both: stage node_feat once; P = nf@W1t + b1; P3 = nf@W3t + b3.
#define PB_W 0
#define PB_A 65536
#define PB_BIAS 131072
#define PB_SMEM (131072 + 1024)

__global__ __launch_bounds__(256, 1)
void pre_both_kernel(const float* __restrict__ A, const float* __restrict__ b1,
                     const float* __restrict__ b3) {
    extern __shared__ char smc[];
    const uint32_t smb = smem_u32(smc);
    const int tid = threadIdx.x;
    const int wid = tid >> 5;
    const int lid = tid & 31;
    float* s_b1 = (float*)(smc + PB_BIAS);
    float* s_b3 = s_b1 + 128;

    {
        const float4* src = (const float4*)(g_WB + 32768);
        float4* dst = (float4*)smc;
        #pragma unroll
        for (int i = 0; i < 16; i++) dst[tid + 256 * i] = src[tid + 256 * i];
    }
    if (tid < 128) { s_b1[tid] = b1[tid]; s_b3[tid] = b3[tid]; }

    const int m0 = blockIdx.x * 128;
    {
        const int r = tid >> 1;
        const int chunk = tid & 1;
        const int gr = m0 + r;
        const bool valid = gr < N_NODES;
        const float* src = A + (size_t)gr * 128 + chunk * 64;
        #pragma unroll
        for (int j = 0; j < 8; j++) {
            float4 v0 = valid ? *(const float4*)(src + j * 8)
                              : make_float4(0.f, 0.f, 0.f, 0.f);
            float4 v1 = valid ? *(const float4*)(src + j * 8 + 4)
                              : make_float4(0.f, 0.f, 0.f, 0.f);
            uint4 hi, lo;
            split8(v0, v1, hi, lo);
            uint32_t off = swz(r * 128 + j * 16);
            *(uint4*)(smc + PB_A + chunk * 16384 + off) = hi;
            *(uint4*)(smc + PB_A + 32768 + chunk * 16384 + off) = lo;
        }
    }
    __syncthreads();

    const int wr0 = wid * 16;
    const int qr = lid >> 2, qc = (lid & 3) * 2;
    const int r0 = wr0 + qr, r1 = r0 + 8;
    const int am = lid >> 3;
    const int arow = wr0 + ((am & 1) << 3) + (lid & 7);
    const int akof = (am >> 1) << 4;
    const int gr0 = m0 + r0, gr1 = m0 + r1;

    float acc[16][4];
    #pragma unroll
    for (int nt = 0; nt < 16; nt++)
        #pragma unroll
        for (int v = 0; v < 4; v++) acc[nt][v] = 0.f;
    gemm128_core(smb, PB_A, PB_W, lid, arow, akof, acc);
    #pragma unroll
    for (int nt = 0; nt < 16; nt++) {
        const int c = nt * 8 + qc;
        if (gr0 < N_NODES)
            *(float2*)(g_P + (size_t)gr0 * 128 + c) = make_float2(
                acc[nt][0] + s_b1[c], acc[nt][1] + s_b1[c + 1]);
        if (gr1 < N_NODES)
            *(float2*)(g_P + (size_t)gr1 * 128 + c) = make_float2(
                acc[nt][2] + s_b1[c], acc[nt][3] + s_b1[c + 1]);
    }
    __syncthreads();
    {
        const float4* src = (const float4*)(g_WB + 32768 + 65536);
        float4* dst = (float4*)smc;
        #pragma unroll
        for (int i = 0; i < 16; i++) dst[tid + 256 * i] = src[tid + 256 * i];
    }
    __syncthreads();
    #pragma unroll
    for (int nt = 0; nt < 16; nt++)
        #pragma unroll
        for (int v = 0; v < 4; v++) acc[nt][v] = 0.f;
    gemm128_core(smb, PB_A, PB_W, lid, arow, akof, acc);
    #pragma unroll
    for (int nt = 0; nt < 16; nt++) {
        const int c = nt * 8 + qc;
        if (gr0 < N_NODES)
            *(float2*)(g_P3 + (size_t)gr0 * 128 + c) = make_float2(
                acc[nt][0] + s_b3[c], acc[nt][1] + s_b3[c + 1]);
        if (gr1 < N_NODES)
            *(float2*)(g_P3 + (size_t)gr1 * 128 + c) = make_float2(
                acc[nt][2] + s_b3[c], acc[nt][3] + s_b3[c + 1]);
    }
}

// ---------------------------------------------------------------------------
// node_fused: mean = sums/max(cnt,1); T = relu(P3 + mean@W23 + flag*b23);
// out = T@W4 + b4.
__global__ __launch_bounds__(256, 1)
void node_fused_kernel(const float* __restrict__ b4, float* __restrict__ out) {
    extern __shared__ char smc[];
    const uint32_t smb = smem_u32(smc);
    const int tid = threadIdx.x;
    const int wid = tid >> 5;
    const int lid = tid & 31;
    float* s_b23 = (float*)(smc + PB_BIAS);
    float* s_b4  = s_b23 + 128;

    {
        const float4* src = (const float4*)(g_WB + 32768 + 2 * 65536);
        float4* dst = (float4*)smc;
        #pragma unroll
        for (int i = 0; i < 16; i++) dst[tid + 256 * i] = src[tid + 256 * i];
    }
    if (tid < 128) { s_b23[tid] = g_b23[tid]; s_b4[tid] = b4[tid]; }

    const int m0 = blockIdx.x * 128;
    {
        const int r = tid >> 1;
        const int chunk = tid & 1;
        const int gr = m0 + r;
        const bool valid = gr < N_NODES;
        float s = valid ? 1.f / fmaxf(g_cnt[gr], 1.f) : 0.f;
        const float* src = g_sums + (size_t)gr * 128 + chunk * 64;
        #pragma unroll
        for (int j = 0; j < 8; j++) {
            float4 v0 = valid ? *(const float4*)(src + j * 8)
                              : make_float4(0.f, 0.f, 0.f, 0.f);
            float4 v1 = valid ? *(const float4*)(src + j * 8 + 4)
                              : make_float4(0.f, 0.f, 0.f, 0.f);
            v0.x *= s; v0.y *= s; v0.z *= s; v0.w *= s;
            v1.x *= s; v1.y *= s; v1.z *= s; v1.w *= s;
            uint4 hi, lo;
            split8(v0, v1, hi, lo);
            uint32_t off = swz(r * 128 + j * 16);
            *(uint4*)(smc + PB_A + chunk * 16384 + off) = hi;
            *(uint4*)(smc + PB_A + 32768 + chunk * 16384 + off) = lo;
        }
    }
    __syncthreads();

    const int wr0 = wid * 16;
    const int qr = lid >> 2, qc = (lid & 3) * 2;
    const int r0 = wr0 + qr, r1 = r0 + 8;
    const int am = lid >> 3;
    const int arow = wr0 + ((am & 1) << 3) + (lid & 7);
    const int akof = (am >> 1) << 4;
    const int gr0 = m0 + r0, gr1 = m0 + r1;

    float acc[16][4];
    #pragma unroll
    for (int nt = 0; nt < 16; nt++)
        #pragma unroll
        for (int v = 0; v < 4; v++) acc[nt][v] = 0.f;
    gemm128_core(smb, PB_A, PB_W, lid, arow, akof, acc);

    {
        const float f0 = (gr0 < N_NODES && g_cnt[gr0] > 0.f) ? 1.f : 0.f;
        const float f1 = (gr1 < N_NODES && g_cnt[gr1] > 0.f) ? 1.f : 0.f;
        #pragma unroll
        for (int nt = 0; nt < 16; nt++) {
            const int c = nt * 8 + qc;
            float t00 = 0.f, t01 = 0.f, t10 = 0.f, t11 = 0.f;
            if (gr0 < N_NODES) {
                float2 p = *(const float2*)(g_P3 + (size_t)gr0 * 128 + c);
                t00 = fmaxf(p.x + acc[nt][0] + f0 * s_b23[c], 0.f);
                t01 = fmaxf(p.y + acc[nt][1] + f0 * s_b23[c + 1], 0.f);
            }
            if (gr1 < N_NODES) {
                float2 p = *(const float2*)(g_P3 + (size_t)gr1 * 128 + c);
                t10 = fmaxf(p.x + acc[nt][2] + f1 * s_b23[c], 0.f);
                t11 = fmaxf(p.y + acc[nt][3] + f1 * s_b23[c + 1], 0.f);
            }
            uint32_t hi0, lo0, hi1, lo1;
            split2(t00, t01, hi0, lo0);
            split2(t10, t11, hi1, lo1);
            const int chunk = (c >> 6) * 16384;
            const int kk2 = (c & 63) * 2;
            *(uint32_t*)(smc + PB_A + chunk + swz(r0 * 128 + kk2)) = hi0;
            *(uint32_t*)(smc + PB_A + chunk + swz(r1 * 128 + kk2)) = hi1;
            *(uint32_t*)(smc + PB_A + 32768 + chunk + swz(r0 * 128 + kk2)) = lo0;
            *(uint32_t*)(smc + PB_A + 32768 + chunk + swz(r1 * 128 + kk2)) = lo1;
        }
    }
    __syncthreads();
    {
        const float4* src = (const float4*)(g_WB + 32768 + 3 * 65536);
        float4* dst = (float4*)smc;
        #pragma unroll
        for (int i = 0; i < 16; i++) dst[tid + 256 * i] = src[tid + 256 * i];
    }
    __syncthreads();
    #pragma unroll
    for (int nt = 0; nt < 16; nt++)
        #pragma unroll
        for (int v = 0; v < 4; v++) acc[nt][v] = 0.f;
    gemm128_core(smb, PB_A, PB_W, lid, arow, akof, acc);
    #pragma unroll
    for (int nt = 0; nt < 16; nt++) {
        const int c = nt * 8 + qc;
        if (gr0 < N_NODES)
            *(float2*)(out + (size_t)gr0 * 128 + c) = make_float2(
                acc[nt][0] + s_b4[c], acc[nt][1] + s_b4[c + 1]);
        if (gr1 < N_NODES)
            *(float2*)(out + (size_t)gr1 * 128 + c) = make_float2(
                acc[nt][2] + s_b4[c], acc[nt][3] + s_b4[c + 1]);
    }
}

// ---------------------------------------------------------------------------
// Edge kernel, 512 threads (16 warps) for latency hiding. Tile = 128 edges.
// Warp (wid) owns rows (wid>>1)*16..+15, cols (wid&1)*64..+63: acc[8][4].
// D1 = ea@W1_bot (bf16x3, K=64); scatter relu(D1 + P[col]) with float4 REDs.
// P rows prefetched to L1 right after indices land (overlaps the GEMM).
// Double-buffered A staging, one __syncthreads per tile.
// SMEM: [0,16K) B1hi | 16K B1lo | 32K A0(hi,lo 32K) | 64K A1 | 96K idx x2
#define SM_B1HI 0
#define SM_B1LO 16384
#define SM_A    32768
#define SM_IDX  98304
#define EDGE_SMEM_BYTES (98304 + 2048)
#define EDGE_THREADS 512

__global__ __launch_bounds__(EDGE_THREADS, 1)
void edge_kernel_mma(const float* __restrict__ ea, const int* __restrict__ eidx,
                     int E, int ntiles) {
    extern __shared__ char smc[];
    const uint32_t smb = smem_u32(smc);
    const int tid = threadIdx.x;
    const int wid = tid >> 5;
    const int lid = tid & 31;

    {   // weights once (32 KB)
        const float4* src = (const float4*)g_WB;
        float4* dst = (float4*)smc;
        for (int i = tid; i < 2048; i += EDGE_THREADS) dst[i] = src[i];
    }

    // staging lane geometry (4 threads/row, 16 floats each)
    const int st_r = tid >> 2;
    const int st_q = tid & 3;

    // MMA lane geometry: row strip + column half per warp
    const int rstrip = (wid >> 1) * 16;
    const int chalf  = (wid & 1) * 64;
    const int qr = lid >> 2;
    const int r0 = rstrip + qr, r1 = r0 + 8;
    const int am = lid >> 3;
    const int arow = rstrip + ((am & 1) << 3) + (lid & 7);
    const int akof = (am >> 1) << 4;
    const int ntoff = lid >> 4;
    const int brow = lid & 7;
    const int bkof = ((lid >> 3) & 1) << 4;
    // epilogue shuffle geometry
    const int cboff = (lid & 2) ? 4 : 0;
    const bool evenlane = ((lid & 1) == 0);
    const int myrow = evenlane ? r0 : r1;

    // ---- stage helper ----
    auto stage = [&](int tile, int q) {
        const int e0s = tile * 128;
        int* rowq = (int*)(smc + SM_IDX) + q * 256;
        int* colq = rowq + 128;
        if (tid < 128) {
            int e = e0s + tid;
            rowq[tid] = (e < E) ? eidx[e] : 0;
        } else if (tid < 256) {
            int t = tid - 128, e = e0s + t;
            colq[t] = (e < E) ? eidx[(size_t)E + e] : 0;
        }
        const int e = e0s + st_r;
        const bool valid = e < E;
        const float* src = ea + (size_t)e * EF + st_q * 16;
        const uint32_t abase = (uint32_t)(SM_A + q * 32768);
        #pragma unroll
        for (int j = 0; j < 2; j++) {
            float4 v0 = valid ? *(const float4*)(src + j * 8)
                              : make_float4(0.f, 0.f, 0.f, 0.f);
            float4 v1 = valid ? *(const float4*)(src + j * 8 + 4)
                              : make_float4(0.f, 0.f, 0.f, 0.f);
            uint4 hi, lo;
            split8(v0, v1, hi, lo);
            uint32_t off = swz(st_r * 128 + st_q * 32 + j * 16);
            *(uint4*)(smc + abase + off) = hi;
            *(uint4*)(smc + abase + 16384 + off) = lo;
        }
    };

    if (blockIdx.x < ntiles) stage(blockIdx.x, 0);
    __syncthreads();

    int p = 0;
    for (int tile = blockIdx.x; tile < ntiles; tile += gridDim.x, p ^= 1) {
        const int e0 = tile * 128;
        const int* rowp = (const int*)(smc + SM_IDX) + p * 256;
        const int* colp = rowp + 128;
        const uint32_t aoff = (uint32_t)(SM_A + p * 32768);

        // ---- prefetch this thread's P-row segment to L1 (overlaps GEMM) ----
        const int srcnode = colp[myrow];
        const float* Pbase = g_P + (size_t)srcnode * 128 + chalf;
        asm volatile("prefetch.global.L1 [%0];" :: "l"(Pbase));
        asm volatile("prefetch.global.L1 [%0];" :: "l"(Pbase + 32));

        // ---- GEMM1: 8 nt per warp (its 64-col half) ----
        float acc[8][4];
        #pragma unroll
        for (int nt = 0; nt < 8; nt++)
            #pragma unroll
            for (int v = 0; v < 4; v++) acc[nt][v] = 0.f;
        #pragma unroll
        for (int kt = 0; kt < 4; kt++) {
            const int kb = kt * 32;
            uint32_t ahi[4], alo[4];
            ldsm_x4(ahi, smb + aoff + swz(arow * 128 + kb + akof));
            ldsm_x4(alo, smb + aoff + 16384 + swz(arow * 128 + kb + akof));
            #pragma unroll
            for (int nt = 0; nt < 8; nt += 2) {
                const int ntg = (chalf >> 3) + nt + ntoff;
                uint32_t bo = swz((ntg * 8 + brow) * 128 + kb + bkof);
                uint32_t bh[4], bl[4];
                ldsm_x4(bh, smb + SM_B1HI + bo);
                ldsm_x4(bl, smb + SM_B1LO + bo);
                mma_bf16(acc[nt],     ahi, bh);
                mma_bf16(acc[nt],     ahi, bl);
                mma_bf16(acc[nt],     alo, bh);
                mma_bf16(acc[nt + 1], ahi, bh + 2);
                mma_bf16(acc[nt + 1], ahi, bl + 2);
                mma_bf16(acc[nt + 1], alo, bh + 2);
            }
        }

        // ---- stage NEXT tile into the other buffer (overlaps epilogue) ----
        const int nxt = tile + gridDim.x;
        if (nxt < ntiles) stage(nxt, 1 - p);

        // ---- epilogue: shuffle to float4; h = relu(D1 + P[col]); RED.F32X4
        {
            const bool valid = (e0 + myrow < E);
            const float* Pn = Pbase + cboff;
            float* Sn = g_sums + (size_t)rowp[myrow] * 128 + chalf + cboff;
            #pragma unroll
            for (int nt = 0; nt < 8; nt++) {
                float sA = evenlane ? acc[nt][2] : acc[nt][0];
                float sB = evenlane ? acc[nt][3] : acc[nt][1];
                float rA = __shfl_xor_sync(0xFFFFFFFFu, sA, 1);
                float rB = __shfl_xor_sync(0xFFFFFFFFu, sB, 1);
                float4 v = evenlane
                    ? make_float4(acc[nt][0], acc[nt][1], rA, rB)
                    : make_float4(rA, rB, acc[nt][2], acc[nt][3]);
                if (valid) {
                    float4 pv = *(const float4*)(Pn + nt * 8);
                    v.x = fmaxf(v.x + pv.x, 0.f);
                    v.y = fmaxf(v.y + pv.y, 0.f);
                    v.z = fmaxf(v.z + pv.z, 0.f);
                    v.w = fmaxf(v.w + pv.w, 0.f);
                    atomicAdd((float4*)(Sn + nt * 8), v);
                }
            }
        }
        if (tid < 128 && e0 + tid < E) atomicAdd(&g_cnt[rowp[tid]], 1.0f);

        __syncthreads();   // buffer 1-p fully staged; buffer p free to rewrite
    }
}

// ---------------------------------------------------------------------------
extern "C" void kernel_launch(void* const* d_in, const int* in_sizes, int n_in,
                              void* d_out, int out_size) {
    const float* node_feat = (const float*)d_in[0];
    const int*   eidx      = (const int*)d_in[1];   // int32 (JAX x64 disabled)
    const float* ea        = (const float*)d_in[2];
    const float* W1 = (const float*)d_in[3];
    const float* b1 = (const float*)d_in[4];
    const float* W2 = (const float*)d_in[5];
    const float* b2 = (const float*)d_in[6];
    const float* W3 = (const float*)d_in[7];
    const float* b3 = (const float*)d_in[8];
    const float* W4 = (const float*)d_in[9];
    const float* b4 = (const float*)d_in[10];
    float* out = (float*)d_out;

    const int E = in_sizes[1] / 2;
    const int NBN = (N_NODES + 127) / 128;   // 391
    const int NBE = (E + 127) / 128;         // 12500

    cudaFuncSetAttribute(pre_both_kernel,
                         cudaFuncAttributeMaxDynamicSharedMemorySize, PB_SMEM);
    cudaFuncSetAttribute(node_fused_kernel,
                         cudaFuncAttributeMaxDynamicSharedMemorySize, PB_SMEM);
    cudaFuncSetAttribute(edge_kernel_mma,
                         cudaFuncAttributeMaxDynamicSharedMemorySize, EDGE_SMEM_BYTES);

    zero_kernel<<<1024, 256>>>();
    prep1_kernel<<<129, 128>>>(W2, W3, b2);
    prep2_kernel<<<64, 256>>>(W1, W3, W4);
    pre_both_kernel<<<NBN, 256, PB_SMEM>>>(node_feat, b1, b3);
    edge_kernel_mma<<<148, EDGE_THREADS, EDGE_SMEM_BYTES>>>(ea, eidx, E, NBE);
    node_fused_kernel<<<NBN, 256, PB_SMEM>>>(b4, out);
}

// round 10
// speedup vs baseline: 1.2541x; 1.0906x over previous
#include <cuda_runtime.h>
#include <cuda_bf16.h>
#include <cstdint>

#define N_NODES 50000
#define HID 128
#define EF 64

// ---------------------------------------------------------------------------
// Scratch (device globals — allocation-free per harness rules)
__device__ float g_P   [(size_t)N_NODES * HID];   // node_feat@W1_top+b1
__device__ float g_P3  [(size_t)N_NODES * HID];   // node_feat@W3_top+b3
__device__ float g_sums[(size_t)N_NODES * HID];   // scatter-add of relu-h
__device__ float g_cnt [N_NODES];
__device__ float g_W23 [128 * 128];               // W2 @ W3_bot (fp32)
__device__ float g_b23 [128];                     // b2 @ W3_bot
// bf16 hi/lo weight images, [N][K] K-major 128B rows, SW128-swizzled.
// [0,16K) B1hi | [16K,32K) B1lo | then 4 node weights x 64KB each.
// widx: 0=W1_top 1=W3_top 2=W23 3=W4
__device__ __align__(16) unsigned char g_WB[32768 + 4 * 65536];

__device__ __forceinline__ uint32_t smem_u32(const void* p) {
    uint32_t a;
    asm("{ .reg .u64 t; cvta.to.shared.u64 t, %1; cvt.u32.u64 %0, t; }"
        : "=r"(a) : "l"(p));
    return a;
}
__device__ __forceinline__ uint32_t swz(uint32_t b) { return b ^ ((b >> 3) & 0x70); }

__device__ __forceinline__ void ldsm_x4(uint32_t* r, uint32_t addr) {
    asm volatile("ldmatrix.sync.aligned.m8n8.x4.shared.b16 {%0,%1,%2,%3}, [%4];"
                 : "=r"(r[0]), "=r"(r[1]), "=r"(r[2]), "=r"(r[3]) : "r"(addr));
}
__device__ __forceinline__ void mma_bf16(float* d, const uint32_t* a, const uint32_t* b) {
    asm volatile("mma.sync.aligned.m16n8k16.row.col.f32.bf16.bf16.f32 "
                 "{%0,%1,%2,%3}, {%4,%5,%6,%7}, {%8,%9}, {%0,%1,%2,%3};"
                 : "+f"(d[0]), "+f"(d[1]), "+f"(d[2]), "+f"(d[3])
                 : "r"(a[0]), "r"(a[1]), "r"(a[2]), "r"(a[3]), "r"(b[0]), "r"(b[1]));
}
__device__ __forceinline__ uint32_t pack_bf16x2(float x, float y) {
    __nv_bfloat162 p = {__float2bfloat16(x), __float2bfloat16(y)};
    return *(uint32_t*)&p;
}
__device__ __forceinline__ void split2(float x, float y, uint32_t& hi, uint32_t& lo) {
    __nv_bfloat16 hx = __float2bfloat16(x), hy = __float2bfloat16(y);
    __nv_bfloat162 ph = {hx, hy};
    hi = *(uint32_t*)&ph;
    lo = pack_bf16x2(x - __bfloat162float(hx), y - __bfloat162float(hy));
}
__device__ __forceinline__ void split8(float4 v0, float4 v1, uint4& hi, uint4& lo) {
    split2(v0.x, v0.y, hi.x, lo.x);
    split2(v0.z, v0.w, hi.y, lo.y);
    split2(v1.x, v1.y, hi.z, lo.z);
    split2(v1.z, v1.w, hi.w, lo.w);
}

// Shared K=128 bf16x3 GEMM core with x4 B-operand ldmatrix (256-thr kernels).
__device__ __forceinline__ void gemm128_core(
    uint32_t smb, uint32_t aoff, uint32_t woff, int lid,
    int arow, int akof, float acc[16][4]) {
    const int ntoff = lid >> 4;
    const int brow = lid & 7;
    const int bkof = ((lid >> 3) & 1) << 4;
    #pragma unroll
    for (int kt = 0; kt < 8; kt++) {
        const int chunk = (kt >> 2) * 16384;
        const int kb = (kt & 3) * 32;
        uint32_t ahi[4], alo[4];
        ldsm_x4(ahi, smb + aoff + chunk + swz(arow * 128 + kb + akof));
        ldsm_x4(alo, smb + aoff + 32768 + chunk + swz(arow * 128 + kb + akof));
        #pragma unroll
        for (int nt = 0; nt < 16; nt += 2) {
            uint32_t bo = swz(((nt + ntoff) * 8 + brow) * 128 + kb + bkof);
            uint32_t bh[4], bl[4];
            ldsm_x4(bh, smb + woff + chunk + bo);
            ldsm_x4(bl, smb + woff + 32768 + chunk + bo);
            mma_bf16(acc[nt],     ahi, bh);
            mma_bf16(acc[nt],     ahi, bl);
            mma_bf16(acc[nt],     alo, bh);
            mma_bf16(acc[nt + 1], ahi, bh + 2);
            mma_bf16(acc[nt + 1], ahi, bl + 2);
            mma_bf16(acc[nt + 1], alo, bh + 2);
        }
    }
}

// ---------------------------------------------------------------------------
__global__ void zero_kernel() {
    const size_t total4 = (size_t)N_NODES * HID / 4;
    float4* s = (float4*)g_sums;
    const float4 z = make_float4(0.f, 0.f, 0.f, 0.f);
    for (size_t i = (size_t)blockIdx.x * blockDim.x + threadIdx.x; i < total4;
         i += (size_t)gridDim.x * blockDim.x)
        s[i] = z;
    for (int i = blockIdx.x * blockDim.x + threadIdx.x; i < N_NODES;
         i += gridDim.x * blockDim.x)
        g_cnt[i] = 0.f;
}

// ---------------------------------------------------------------------------
// W23 = W2 @ W3[128:256], b23 = b2 @ W3[128:256]
__global__ void prep1_kernel(const float* __restrict__ W2,
                             const float* __restrict__ W3,
                             const float* __restrict__ b2) {
    __shared__ float srow[128];
    const int r = blockIdx.x;
    const int c = threadIdx.x;
    srow[c] = (r < 128) ? W2[r * 128 + c] : b2[c];
    __syncthreads();
    float acc = 0.f;
    #pragma unroll 4
    for (int k = 0; k < 128; k++)
        acc += srow[k] * W3[(128 + k) * 128 + c];
    if (r < 128) g_W23[r * 128 + c] = acc;
    else         g_b23[c] = acc;
}

// ---------------------------------------------------------------------------
__global__ void prep2_kernel(const float* __restrict__ W1,
                             const float* __restrict__ W3,
                             const float* __restrict__ W4) {
    const int tid = blockIdx.x * blockDim.x + threadIdx.x;
    const int nth = gridDim.x * blockDim.x;
    for (int i = tid; i < 128 * 64; i += nth) {       // edge B1 = W1 rows 128..191
        int n = i >> 6, k = i & 63;
        float v = W1[(128 + k) * 128 + n];
        __nv_bfloat16 h = __float2bfloat16(v);
        __nv_bfloat16 l = __float2bfloat16(v - __bfloat162float(h));
        uint32_t off = swz(n * 128 + k * 2);
        *(__nv_bfloat16*)(g_WB + off)         = h;
        *(__nv_bfloat16*)(g_WB + 16384 + off) = l;
    }
    for (int i = tid; i < 4 * 128 * 128; i += nth) {  // node weights
        int widx = i >> 14, j = i & 16383;
        int n = j >> 7, k = j & 127;
        float v;
        if      (widx == 0) v = W1[k * 128 + n];
        else if (widx == 1) v = W3[k * 128 + n];
        else if (widx == 2) v = g_W23[k * 128 + n];
        else                v = W4[k * 128 + n];
        __nv_bfloat16 h = __float2bfloat16(v);
        __nv_bfloat16 l = __float2bfloat16(v - __bfloat162float(h));
        int c = k >> 6, kk = k & 63;
        uint32_t off = swz(n * 128 + kk * 2);
        unsigned char* base = g_WB + 32768 + widx * 65536;
        *(__nv_bfloat16*)(base + c * 16384 + off)         = h;
        *(__nv_bfloat16*)(base + 32768 + c * 16384 + off) = l;
    }
}

// ---------------------------------------------------------------------------
// pre_both: stage node_feat once; P = nf@W1t + b1; P3 = nf@W3t + b3.
#define PB_W 0
#define PB_A 65536
#define PB_BIAS 131072
#define PB_SMEM (131072 + 1024)

__global__ __launch_bounds__(256, 1)
void pre_both_kernel(const float* __restrict__ A, const float* __restrict__ b1,
                     const float* __restrict__ b3) {
    extern __shared__ char smc[];
    const uint32_t smb = smem_u32(smc);
    const int tid = threadIdx.x;
    const int wid = tid >> 5;
    const int lid = tid & 31;
    float* s_b1 = (float*)(smc + PB_BIAS);
    float* s_b3 = s_b1 + 128;

    {
        const float4* src = (const float4*)(g_WB + 32768);
        float4* dst = (float4*)smc;
        #pragma unroll
        for (int i = 0; i < 16; i++) dst[tid + 256 * i] = src[tid + 256 * i];
    }
    if (tid < 128) { s_b1[tid] = b1[tid]; s_b3[tid] = b3[tid]; }

    const int m0 = blockIdx.x * 128;
    {
        const int r = tid >> 1;
        const int chunk = tid & 1;
        const int gr = m0 + r;
        const bool valid = gr < N_NODES;
        const float* src = A + (size_t)gr * 128 + chunk * 64;
        #pragma unroll
        for (int j = 0; j < 8; j++) {
            float4 v0 = valid ? *(const float4*)(src + j * 8)
                              : make_float4(0.f, 0.f, 0.f, 0.f);
            float4 v1 = valid ? *(const float4*)(src + j * 8 + 4)
                              : make_float4(0.f, 0.f, 0.f, 0.f);
            uint4 hi, lo;
            split8(v0, v1, hi, lo);
            uint32_t off = swz(r * 128 + j * 16);
            *(uint4*)(smc + PB_A + chunk * 16384 + off) = hi;
            *(uint4*)(smc + PB_A + 32768 + chunk * 16384 + off) = lo;
        }
    }
    __syncthreads();

    const int wr0 = wid * 16;
    const int qr = lid >> 2, qc = (lid & 3) * 2;
    const int r0 = wr0 + qr, r1 = r0 + 8;
    const int am = lid >> 3;
    const int arow = wr0 + ((am & 1) << 3) + (lid & 7);
    const int akof = (am >> 1) << 4;
    const int gr0 = m0 + r0, gr1 = m0 + r1;

    float acc[16][4];
    #pragma unroll
    for (int nt = 0; nt < 16; nt++)
        #pragma unroll
        for (int v = 0; v < 4; v++) acc[nt][v] = 0.f;
    gemm128_core(smb, PB_A, PB_W, lid, arow, akof, acc);
    #pragma unroll
    for (int nt = 0; nt < 16; nt++) {
        const int c = nt * 8 + qc;
        if (gr0 < N_NODES)
            *(float2*)(g_P + (size_t)gr0 * 128 + c) = make_float2(
                acc[nt][0] + s_b1[c], acc[nt][1] + s_b1[c + 1]);
        if (gr1 < N_NODES)
            *(float2*)(g_P + (size_t)gr1 * 128 + c) = make_float2(
                acc[nt][2] + s_b1[c], acc[nt][3] + s_b1[c + 1]);
    }
    __syncthreads();
    {
        const float4* src = (const float4*)(g_WB + 32768 + 65536);
        float4* dst = (float4*)smc;
        #pragma unroll
        for (int i = 0; i < 16; i++) dst[tid + 256 * i] = src[tid + 256 * i];
    }
    __syncthreads();
    #pragma unroll
    for (int nt = 0; nt < 16; nt++)
        #pragma unroll
        for (int v = 0; v < 4; v++) acc[nt][v] = 0.f;
    gemm128_core(smb, PB_A, PB_W, lid, arow, akof, acc);
    #pragma unroll
    for (int nt = 0; nt < 16; nt++) {
        const int c = nt * 8 + qc;
        if (gr0 < N_NODES)
            *(float2*)(g_P3 + (size_t)gr0 * 128 + c) = make_float2(
                acc[nt][0] + s_b3[c], acc[nt][1] + s_b3[c + 1]);
        if (gr1 < N_NODES)
            *(float2*)(g_P3 + (size_t)gr1 * 128 + c) = make_float2(
                acc[nt][2] + s_b3[c], acc[nt][3] + s_b3[c + 1]);
    }
}

// ---------------------------------------------------------------------------
// node_fused: mean = sums/max(cnt,1); T = relu(P3 + mean@W23 + flag*b23);
// out = T@W4 + b4.
__global__ __launch_bounds__(256, 1)
void node_fused_kernel(const float* __restrict__ b4, float* __restrict__ out) {
    extern __shared__ char smc[];
    const uint32_t smb = smem_u32(smc);
    const int tid = threadIdx.x;
    const int wid = tid >> 5;
    const int lid = tid & 31;
    float* s_b23 = (float*)(smc + PB_BIAS);
    float* s_b4  = s_b23 + 128;

    {
        const float4* src = (const float4*)(g_WB + 32768 + 2 * 65536);
        float4* dst = (float4*)smc;
        #pragma unroll
        for (int i = 0; i < 16; i++) dst[tid + 256 * i] = src[tid + 256 * i];
    }
    if (tid < 128) { s_b23[tid] = g_b23[tid]; s_b4[tid] = b4[tid]; }

    const int m0 = blockIdx.x * 128;
    {
        const int r = tid >> 1;
        const int chunk = tid & 1;
        const int gr = m0 + r;
        const bool valid = gr < N_NODES;
        float s = valid ? 1.f / fmaxf(g_cnt[gr], 1.f) : 0.f;
        const float* src = g_sums + (size_t)gr * 128 + chunk * 64;
        #pragma unroll
        for (int j = 0; j < 8; j++) {
            float4 v0 = valid ? *(const float4*)(src + j * 8)
                              : make_float4(0.f, 0.f, 0.f, 0.f);
            float4 v1 = valid ? *(const float4*)(src + j * 8 + 4)
                              : make_float4(0.f, 0.f, 0.f, 0.f);
            v0.x *= s; v0.y *= s; v0.z *= s; v0.w *= s;
            v1.x *= s; v1.y *= s; v1.z *= s; v1.w *= s;
            uint4 hi, lo;
            split8(v0, v1, hi, lo);
            uint32_t off = swz(r * 128 + j * 16);
            *(uint4*)(smc + PB_A + chunk * 16384 + off) = hi;
            *(uint4*)(smc + PB_A + 32768 + chunk * 16384 + off) = lo;
        }
    }
    __syncthreads();

    const int wr0 = wid * 16;
    const int qr = lid >> 2, qc = (lid & 3) * 2;
    const int r0 = wr0 + qr, r1 = r0 + 8;
    const int am = lid >> 3;
    const int arow = wr0 + ((am & 1) << 3) + (lid & 7);
    const int akof = (am >> 1) << 4;
    const int gr0 = m0 + r0, gr1 = m0 + r1;

    float acc[16][4];
    #pragma unroll
    for (int nt = 0; nt < 16; nt++)
        #pragma unroll
        for (int v = 0; v < 4; v++) acc[nt][v] = 0.f;
    gemm128_core(smb, PB_A, PB_W, lid, arow, akof, acc);

    {
        const float f0 = (gr0 < N_NODES && g_cnt[gr0] > 0.f) ? 1.f : 0.f;
        const float f1 = (gr1 < N_NODES && g_cnt[gr1] > 0.f) ? 1.f : 0.f;
        #pragma unroll
        for (int nt = 0; nt < 16; nt++) {
            const int c = nt * 8 + qc;
            float t00 = 0.f, t01 = 0.f, t10 = 0.f, t11 = 0.f;
            if (gr0 < N_NODES) {
                float2 p = *(const float2*)(g_P3 + (size_t)gr0 * 128 + c);
                t00 = fmaxf(p.x + acc[nt][0] + f0 * s_b23[c], 0.f);
                t01 = fmaxf(p.y + acc[nt][1] + f0 * s_b23[c + 1], 0.f);
            }
            if (gr1 < N_NODES) {
                float2 p = *(const float2*)(g_P3 + (size_t)gr1 * 128 + c);
                t10 = fmaxf(p.x + acc[nt][2] + f1 * s_b23[c], 0.f);
                t11 = fmaxf(p.y + acc[nt][3] + f1 * s_b23[c + 1], 0.f);
            }
            uint32_t hi0, lo0, hi1, lo1;
            split2(t00, t01, hi0, lo0);
            split2(t10, t11, hi1, lo1);
            const int chunk = (c >> 6) * 16384;
            const int kk2 = (c & 63) * 2;
            *(uint32_t*)(smc + PB_A + chunk + swz(r0 * 128 + kk2)) = hi0;
            *(uint32_t*)(smc + PB_A + chunk + swz(r1 * 128 + kk2)) = hi1;
            *(uint32_t*)(smc + PB_A + 32768 + chunk + swz(r0 * 128 + kk2)) = lo0;
            *(uint32_t*)(smc + PB_A + 32768 + chunk + swz(r1 * 128 + kk2)) = lo1;
        }
    }
    __syncthreads();
    {
        const float4* src = (const float4*)(g_WB + 32768 + 3 * 65536);
        float4* dst = (float4*)smc;
        #pragma unroll
        for (int i = 0; i < 16; i++) dst[tid + 256 * i] = src[tid + 256 * i];
    }
    __syncthreads();
    #pragma unroll
    for (int nt = 0; nt < 16; nt++)
        #pragma unroll
        for (int v = 0; v < 4; v++) acc[nt][v] = 0.f;
    gemm128_core(smb, PB_A, PB_W, lid, arow, akof, acc);
    #pragma unroll
    for (int nt = 0; nt < 16; nt++) {
        const int c = nt * 8 + qc;
        if (gr0 < N_NODES)
            *(float2*)(out + (size_t)gr0 * 128 + c) = make_float2(
                acc[nt][0] + s_b4[c], acc[nt][1] + s_b4[c + 1]);
        if (gr1 < N_NODES)
            *(float2*)(out + (size_t)gr1 * 128 + c) = make_float2(
                acc[nt][2] + s_b4[c], acc[nt][3] + s_b4[c + 1]);
    }
}

// ---------------------------------------------------------------------------
// Edge kernel: 256 threads, 2 CTAs/SM (two independent sync domains).
// CTA tile = 64 edges; 8 warps, warp owns rows (wid>>1)*16..+15, cols
// (wid&1)*64..+63 (acc[8][4]). Double-buffered A staging, prefetch of P rows,
// one __syncthreads per tile. When one CTA is in a barrier/memory phase, the
// co-resident CTA's warps keep the tensor pipe fed.
// SMEM: [0,16K) B1hi | 16K B1lo | 32K A0hi | 40K A0lo | 48K A1hi | 56K A1lo
//       | 64K idx (2 x 128 ints)
#define SM_B1HI 0
#define SM_B1LO 16384
#define SM_A    32768
#define SM_IDX  65536
#define EDGE_SMEM_BYTES (65536 + 1280)
#define EDGE_THREADS 256
#define TILE_E 64

__global__ __launch_bounds__(EDGE_THREADS, 2)
void edge_kernel_mma(const float* __restrict__ ea, const int* __restrict__ eidx,
                     int E, int ntiles) {
    extern __shared__ char smc[];
    const uint32_t smb = smem_u32(smc);
    const int tid = threadIdx.x;
    const int wid = tid >> 5;
    const int lid = tid & 31;

    {   // weights once (32 KB)
        const float4* src = (const float4*)g_WB;
        float4* dst = (float4*)smc;
        for (int i = tid; i < 2048; i += EDGE_THREADS) dst[i] = src[i];
    }

    // staging lane geometry (4 threads/row, 16 floats each; 64 rows)
    const int st_r = tid >> 2;
    const int st_q = tid & 3;

    // MMA lane geometry: 4 row strips x 2 col halves
    const int rstrip = (wid >> 1) * 16;
    const int chalf  = (wid & 1) * 64;
    const int qr = lid >> 2;
    const int r0 = rstrip + qr, r1 = r0 + 8;
    const int am = lid >> 3;
    const int arow = rstrip + ((am & 1) << 3) + (lid & 7);
    const int akof = (am >> 1) << 4;
    const int ntoff = lid >> 4;
    const int brow = lid & 7;
    const int bkof = ((lid >> 3) & 1) << 4;
    // epilogue shuffle geometry
    const int cboff = (lid & 2) ? 4 : 0;
    const bool evenlane = ((lid & 1) == 0);
    const int myrow = evenlane ? r0 : r1;

    // ---- stage helper: 64-edge tile into buffer q ----
    auto stage = [&](int tile, int q) {
        const int e0s = tile * TILE_E;
        int* rowq = (int*)(smc + SM_IDX) + q * 128;
        int* colq = rowq + 64;
        if (tid < 64) {
            int e = e0s + tid;
            rowq[tid] = (e < E) ? eidx[e] : 0;
        } else if (tid < 128) {
            int t = tid - 64, e = e0s + t;
            colq[t] = (e < E) ? eidx[(size_t)E + e] : 0;
        }
        const int e = e0s + st_r;
        const bool valid = e < E;
        const float* src = ea + (size_t)e * EF + st_q * 16;
        const uint32_t abase = (uint32_t)(SM_A + q * 16384);
        #pragma unroll
        for (int j = 0; j < 2; j++) {
            float4 v0 = valid ? *(const float4*)(src + j * 8)
                              : make_float4(0.f, 0.f, 0.f, 0.f);
            float4 v1 = valid ? *(const float4*)(src + j * 8 + 4)
                              : make_float4(0.f, 0.f, 0.f, 0.f);
            uint4 hi, lo;
            split8(v0, v1, hi, lo);
            uint32_t off = swz(st_r * 128 + st_q * 32 + j * 16);
            *(uint4*)(smc + abase + off) = hi;
            *(uint4*)(smc + abase + 8192 + off) = lo;
        }
    };

    if (blockIdx.x < ntiles) stage(blockIdx.x, 0);
    __syncthreads();

    int p = 0;
    for (int tile = blockIdx.x; tile < ntiles; tile += gridDim.x, p ^= 1) {
        const int e0 = tile * TILE_E;
        const int* rowp = (const int*)(smc + SM_IDX) + p * 128;
        const int* colp = rowp + 64;
        const uint32_t aoff = (uint32_t)(SM_A + p * 16384);

        // ---- prefetch this thread's P-row segment to L1 (overlaps GEMM) ----
        const int srcnode = colp[myrow];
        const float* Pbase = g_P + (size_t)srcnode * 128 + chalf;
        asm volatile("prefetch.global.L1 [%0];" :: "l"(Pbase));
        asm volatile("prefetch.global.L1 [%0];" :: "l"(Pbase + 32));

        // ---- GEMM1: 8 nt per warp (its 64-col half), K=64 ----
        float acc[8][4];
        #pragma unroll
        for (int nt = 0; nt < 8; nt++)
            #pragma unroll
            for (int v = 0; v < 4; v++) acc[nt][v] = 0.f;
        #pragma unroll
        for (int kt = 0; kt < 4; kt++) {
            const int kb = kt * 32;
            uint32_t ahi[4], alo[4];
            ldsm_x4(ahi, smb + aoff + swz(arow * 128 + kb + akof));
            ldsm_x4(alo, smb + aoff + 8192 + swz(arow * 128 + kb + akof));
            #pragma unroll
            for (int nt = 0; nt < 8; nt += 2) {
                const int ntg = (chalf >> 3) + nt + ntoff;
                uint32_t bo = swz((ntg * 8 + brow) * 128 + kb + bkof);
                uint32_t bh[4], bl[4];
                ldsm_x4(bh, smb + SM_B1HI + bo);
                ldsm_x4(bl, smb + SM_B1LO + bo);
                mma_bf16(acc[nt],     ahi, bh);
                mma_bf16(acc[nt],     ahi, bl);
                mma_bf16(acc[nt],     alo, bh);
                mma_bf16(acc[nt + 1], ahi, bh + 2);
                mma_bf16(acc[nt + 1], ahi, bl + 2);
                mma_bf16(acc[nt + 1], alo, bh + 2);
            }
        }

        // ---- stage NEXT tile into the other buffer (overlaps epilogue) ----
        const int nxt = tile + gridDim.x;
        if (nxt < ntiles) stage(nxt, 1 - p);

        // ---- epilogue: shuffle to float4; h = relu(D1 + P[col]); RED.F32X4
        {
            const bool valid = (e0 + myrow < E);
            const float* Pn = Pbase + cboff;
            float* Sn = g_sums + (size_t)rowp[myrow] * 128 + chalf + cboff;
            #pragma unroll
            for (int nt = 0; nt < 8; nt++) {
                float sA = evenlane ? acc[nt][2] : acc[nt][0];
                float sB = evenlane ? acc[nt][3] : acc[nt][1];
                float rA = __shfl_xor_sync(0xFFFFFFFFu, sA, 1);
                float rB = __shfl_xor_sync(0xFFFFFFFFu, sB, 1);
                float4 v = evenlane
                    ? make_float4(acc[nt][0], acc[nt][1], rA, rB)
                    : make_float4(rA, rB, acc[nt][2], acc[nt][3]);
                if (valid) {
                    float4 pv = *(const float4*)(Pn + nt * 8);
                    v.x = fmaxf(v.x + pv.x, 0.f);
                    v.y = fmaxf(v.y + pv.y, 0.f);
                    v.z = fmaxf(v.z + pv.z, 0.f);
                    v.w = fmaxf(v.w + pv.w, 0.f);
                    atomicAdd((float4*)(Sn + nt * 8), v);
                }
            }
        }
        if (tid < 64 && e0 + tid < E) atomicAdd(&g_cnt[rowp[tid]], 1.0f);

        __syncthreads();   // buffer 1-p fully staged; buffer p free to rewrite
    }
}

// ---------------------------------------------------------------------------
extern "C" void kernel_launch(void* const* d_in, const int* in_sizes, int n_in,
                              void* d_out, int out_size) {
    const float* node_feat = (const float*)d_in[0];
    const int*   eidx      = (const int*)d_in[1];   // int32 (JAX x64 disabled)
    const float* ea        = (const float*)d_in[2];
    const float* W1 = (const float*)d_in[3];
    const float* b1 = (const float*)d_in[4];
    const float* W2 = (const float*)d_in[5];
    const float* b2 = (const float*)d_in[6];
    const float* W3 = (const float*)d_in[7];
    const float* b3 = (const float*)d_in[8];
    const float* W4 = (const float*)d_in[9];
    const float* b4 = (const float*)d_in[10];
    float* out = (float*)d_out;

    const int E = in_sizes[1] / 2;
    const int NBN = (N_NODES + 127) / 128;      // 391
    const int NTE = (E + TILE_E - 1) / TILE_E;  // 25000

    cudaFuncSetAttribute(pre_both_kernel,
                         cudaFuncAttributeMaxDynamicSharedMemorySize, PB_SMEM);
    cudaFuncSetAttribute(node_fused_kernel,
                         cudaFuncAttributeMaxDynamicSharedMemorySize, PB_SMEM);
    cudaFuncSetAttribute(edge_kernel_mma,
                         cudaFuncAttributeMaxDynamicSharedMemorySize, EDGE_SMEM_BYTES);

    zero_kernel<<<1024, 256>>>();
    prep1_kernel<<<129, 128>>>(W2, W3, b2);
    prep2_kernel<<<64, 256>>>(W1, W3, W4);
    pre_both_kernel<<<NBN, 256, PB_SMEM>>>(node_feat, b1, b3);
    edge_kernel_mma<<<296, EDGE_THREADS, EDGE_SMEM_BYTES>>>(ea, eidx, E, NTE);
    node_fused_kernel<<<NBN, 256, PB_SMEM>>>(b4, out);
}